// round 2
// baseline (speedup 1.0000x reference)
#include <cuda_runtime.h>

#define BB 2
#define NN 40000
#define EE 400000
#define RR 64
#define DD 64
#define LLAYERS 6
#define MASKW 1250  // (NN+31)/32

// Scratch (allocation-free rule: __device__ globals)
__device__ __align__(16) float g_x[BB * NN * DD];    // 20.5 MB
__device__ __align__(16) float g_agg[BB * NN * DD];  // 20.5 MB  (invariant: all-zero at launch entry/exit)
__device__ __align__(16) float g_rel[BB * RR * DD];
__device__ __align__(16) float g_query[BB * DD];
__device__ __align__(16) float g_qpart[BB * 2 * DD];
__device__ unsigned g_mask[BB * MASKW];  // bit set => x row may be nonzero
__device__ int g_list[BB * NN];
__device__ int g_count[BB];
__device__ int g_dense;  // 1 => zero rows would produce nonzero output; process everything

// ---------------------------------------------------------------------------
// prep: clear masks, query[b] = rel_reps[b, r_index[b]], set h bit,
//       qpart = query @ mlp_w[64:] + mlp_b, dense-fallback flag.
// ---------------------------------------------------------------------------
__global__ void prep_kernel(const float* __restrict__ rel_reps,
                            const int* __restrict__ r_index,
                            const int* __restrict__ h_index,
                            const float* __restrict__ mlp_w,
                            const float* __restrict__ mlp_b,
                            const float* __restrict__ lin_b,
                            const float* __restrict__ ln_g,
                            const float* __restrict__ ln_b) {
    __shared__ float q_s[BB * DD];
    int t = threadIdx.x;  // 256
    for (int i = t; i < BB * MASKW; i += 256) g_mask[i] = 0u;
    if (t < BB * DD) {
        int b = t / DD, d = t % DD;
        float v = rel_reps[(b * RR + r_index[b]) * DD + d];
        g_query[t] = v;
        q_s[t] = v;
    }
    __syncthreads();
    if (t < BB) {
        int h = h_index[t];
        g_mask[t * MASKW + (h >> 5)] = 1u << (h & 31);
    }
    // dense-fallback: would an all-zero input row yield nonzero output?
    if (t == 0) {
        int dense = 0;
        for (int l = 0; l < LLAYERS; l++) {
            const float* lb = lin_b + l * DD;
            float mu = 0.f;
            for (int d = 0; d < DD; d++) mu += lb[d];
            mu *= (1.f / DD);
            float var = 0.f;
            for (int d = 0; d < DD; d++) {
                float dv = lb[d] - mu;
                var += dv * dv;
            }
            var *= (1.f / DD);
            float inv = rsqrtf(var + 1e-5f);
            for (int d = 0; d < DD; d++) {
                float o = (lb[d] - mu) * inv * ln_g[l * DD + d] + ln_b[l * DD + d];
                if (o > 0.f) dense = 1;
            }
        }
        g_dense = dense;
    }
    int b = t / 128, e = t % 128;
    float acc = mlp_b[e];
#pragma unroll
    for (int k = 0; k < DD; k++)
        acc = fmaf(q_s[b * DD + k], mlp_w[(DD + k) * 128 + e], acc);
    g_qpart[b * 128 + e] = acc;
}

// ---------------------------------------------------------------------------
// init x: zeros everywhere, query at h_index[b]
// ---------------------------------------------------------------------------
__global__ void init_x(const int* __restrict__ h_index) {
    int gid = blockIdx.x * 256 + threadIdx.x;
    const int per_b = NN * DD / 4;  // 640000 float4
    if (gid >= BB * per_b) return;
    int b = gid / per_b;
    int r = gid - b * per_b;
    int n = r >> 4;
    int d4 = r & 15;
    float4 v = make_float4(0.f, 0.f, 0.f, 0.f);
    if (n == __ldg(&h_index[b]))
        v = *(const float4*)&g_query[b * DD + d4 * 4];
    ((float4*)g_x)[gid] = v;
}

// ---------------------------------------------------------------------------
// per-layer relation projection + (first block per batch) count reset +
// boundary row agg[b,h] = query (agg row is zero here by invariant).
// ---------------------------------------------------------------------------
__global__ void relproj_kernel(const float* __restrict__ rel_reps,
                               const float* __restrict__ pw1,
                               const float* __restrict__ pb1,
                               const float* __restrict__ pw2,
                               const float* __restrict__ pb2,
                               const int* __restrict__ h_index, int l) {
    int br = blockIdx.x;  // b*RR + r
    int b = br >> 6;
    int e = threadIdx.x;  // 64
    __shared__ float in_s[DD];
    __shared__ float hid_s[DD];
    in_s[e] = rel_reps[br * DD + e];
    __syncthreads();
    const float* W1 = pw1 + l * DD * DD;
    float acc = pb1[l * DD + e];
#pragma unroll 16
    for (int k = 0; k < DD; k++) acc = fmaf(in_s[k], W1[k * DD + e], acc);
    hid_s[e] = fmaxf(acc, 0.f);
    __syncthreads();
    const float* W2 = pw2 + l * DD * DD;
    float acc2 = pb2[l * DD + e];
#pragma unroll 16
    for (int k = 0; k < DD; k++) acc2 = fmaf(hid_s[k], W2[k * DD + e], acc2);
    g_rel[br * DD + e] = acc2;

    if ((br & 63) == 0) {
        if (e == 0) g_count[b] = 0;
        int h = __ldg(&h_index[b]);
        g_agg[(b * NN + h) * DD + e] = g_query[b * DD + e];
    }
}

// ---------------------------------------------------------------------------
// message: one thread per edge. Skip edges with inactive src (exact: zero
// rows contribute zero). For active edges: agg[dst] += x[src]*rel[type],
// mark dst active. rel rows hit L1 (64KB total).
// ---------------------------------------------------------------------------
__global__ void message_kernel(const int* __restrict__ edge_index,
                               const int* __restrict__ edge_type) {
    int gid = blockIdx.x * 256 + threadIdx.x;
    if (gid >= BB * EE) return;
    int b = (gid >= EE) ? 1 : 0;
    int e = gid - b * EE;
    int src = __ldg(&edge_index[e]);
    unsigned mw = g_mask[b * MASKW + (src >> 5)];
    if (!((mw >> (src & 31)) & 1u)) return;
    int dst = __ldg(&edge_index[EE + e]);
    int ty = __ldg(&edge_type[e]);
    unsigned dw = g_mask[b * MASKW + (dst >> 5)];
    if (!((dw >> (dst & 31)) & 1u))
        atomicOr(&g_mask[b * MASKW + (dst >> 5)], 1u << (dst & 31));
    const float4* xr = (const float4*)(g_x + (b * NN + src) * DD);
    const float4* rr = (const float4*)(g_rel + (b * RR + ty) * DD);
    float* ar = g_agg + (b * NN + dst) * DD;
#pragma unroll
    for (int c = 0; c < 16; c++) {
        float4 xv = xr[c];
        if (xv.x == 0.f && xv.y == 0.f && xv.z == 0.f && xv.w == 0.f) continue;
        float4 rv = __ldg(&rr[c]);
        asm volatile("red.global.add.v4.f32 [%0], {%1,%2,%3,%4};" ::"l"(ar + c * 4),
                     "f"(xv.x * rv.x), "f"(xv.y * rv.y), "f"(xv.z * rv.z),
                     "f"(xv.w * rv.w)
                     : "memory");
    }
}

// ---------------------------------------------------------------------------
// compact: mask -> list (order-independent). Dense fallback includes all.
// ---------------------------------------------------------------------------
__global__ void compact_kernel() {
    int gid = blockIdx.x * 256 + threadIdx.x;
    if (gid >= BB * NN) return;
    int b = gid / NN;
    int n = gid - b * NN;
    bool act;
    if (g_dense) {
        act = true;
        if ((n & 31) == 0) g_mask[b * MASKW + (n >> 5)] = 0xffffffffu;
    } else {
        act = (g_mask[b * MASKW + (n >> 5)] >> (n & 31)) & 1u;
    }
    if (act) {
        int p = atomicAdd(&g_count[b], 1);
        g_list[b * NN + p] = n;
    }
}

// ---------------------------------------------------------------------------
// fused: for active rows: x = relu(LN(cat(x,agg)@W + b)) + x; agg row -> 0.
// block = 64 list entries, 256 threads, 4x4 register tile per thread.
// ---------------------------------------------------------------------------
__global__ void linear_kernel(const float* __restrict__ lin_w,
                              const float* __restrict__ lin_b,
                              const float* __restrict__ ln_g,
                              const float* __restrict__ ln_b, int l) {
    extern __shared__ float smem[];
    float* W_s = smem;               // [128][64] = 32KB
    float* cat_s = smem + 128 * 64;  // [k][node] transposed = 32KB
    __shared__ int idx_s[64];
    int b = blockIdx.y;
    int base = blockIdx.x * 64;
    int t = threadIdx.x;  // 256
    int cnt = g_count[b];
    if (base >= cnt) return;

    if (t < 64) idx_s[t] = (base + t < cnt) ? g_list[b * NN + base + t] : -1;

    // load weights (8192 floats)
    const float4* Wg = (const float4*)(lin_w + l * 128 * 64);
    float4* Ws4 = (float4*)W_s;
#pragma unroll
    for (int i = 0; i < 8; i++) Ws4[t + i * 256] = Wg[t + i * 256];
    __syncthreads();

    // gather cat = [x ; agg] rows (via list) transposed into smem
    int nl = t & 63;
    int c0 = t >> 6;  // 0..3
    int idx = idx_s[nl];
    const float* xb = g_x + (b * NN + idx) * DD;
    const float* ab = g_agg + (b * NN + idx) * DD;
#pragma unroll
    for (int i = 0; i < 4; i++) {
        int cc = c0 + i * 4;  // float4 col 0..15
        float4 v = make_float4(0.f, 0.f, 0.f, 0.f);
        float4 a = make_float4(0.f, 0.f, 0.f, 0.f);
        if (idx >= 0) {
            v = *(const float4*)&xb[cc * 4];
            a = *(const float4*)&ab[cc * 4];
        }
        cat_s[(cc * 4 + 0) * 64 + nl] = v.x;
        cat_s[(cc * 4 + 1) * 64 + nl] = v.y;
        cat_s[(cc * 4 + 2) * 64 + nl] = v.z;
        cat_s[(cc * 4 + 3) * 64 + nl] = v.w;
        cat_s[(64 + cc * 4 + 0) * 64 + nl] = a.x;
        cat_s[(64 + cc * 4 + 1) * 64 + nl] = a.y;
        cat_s[(64 + cc * 4 + 2) * 64 + nl] = a.z;
        cat_s[(64 + cc * 4 + 3) * 64 + nl] = a.w;
    }
    __syncthreads();

    int tn = t >> 4;  // node group (4 nodes)
    int td = t & 15;  // dim group  (4 dims)
    float4 bias4 = *(const float4*)&lin_b[l * 64 + td * 4];
    float acc[4][4];
#pragma unroll
    for (int i = 0; i < 4; i++) {
        acc[i][0] = bias4.x; acc[i][1] = bias4.y;
        acc[i][2] = bias4.z; acc[i][3] = bias4.w;
    }

#pragma unroll 4
    for (int k = 0; k < 128; ++k) {
        const float4 a4 = *(const float4*)(cat_s + k * 64 + tn * 4);
        const float4 w4 = *(const float4*)(W_s + k * 64 + td * 4);
        float aa[4] = {a4.x, a4.y, a4.z, a4.w};
        float ww[4] = {w4.x, w4.y, w4.z, w4.w};
#pragma unroll
        for (int i = 0; i < 4; i++)
#pragma unroll
            for (int j = 0; j < 4; j++)
                acc[i][j] = fmaf(aa[i], ww[j], acc[i][j]);
    }

    // fused LayerNorm + relu + shortcut; zero agg row for next layer
    float4 g4 = *(const float4*)&ln_g[l * 64 + td * 4];
    float4 bb4 = *(const float4*)&ln_b[l * 64 + td * 4];
    float lng[4] = {g4.x, g4.y, g4.z, g4.w};
    float lnb[4] = {bb4.x, bb4.y, bb4.z, bb4.w};
#pragma unroll
    for (int i = 0; i < 4; i++) {
        float s = acc[i][0] + acc[i][1] + acc[i][2] + acc[i][3];
        float s2 = acc[i][0] * acc[i][0] + acc[i][1] * acc[i][1] +
                   acc[i][2] * acc[i][2] + acc[i][3] * acc[i][3];
#pragma unroll
        for (int m = 1; m < 16; m <<= 1) {
            s += __shfl_xor_sync(0xffffffffu, s, m);
            s2 += __shfl_xor_sync(0xffffffffu, s2, m);
        }
        float mu = s * (1.f / 64.f);
        float var = s2 * (1.f / 64.f) - mu * mu;
        float inv = rsqrtf(var + 1e-5f);
        int row = idx_s[tn * 4 + i];
        if (row >= 0) {
            float* xr = g_x + (b * NN + row) * DD + td * 4;
            float4 xold = *(const float4*)xr;
            float4 o;
            o.x = fmaxf((acc[i][0] - mu) * inv * lng[0] + lnb[0], 0.f) + xold.x;
            o.y = fmaxf((acc[i][1] - mu) * inv * lng[1] + lnb[1], 0.f) + xold.y;
            o.z = fmaxf((acc[i][2] - mu) * inv * lng[2] + lnb[2], 0.f) + xold.z;
            o.w = fmaxf((acc[i][3] - mu) * inv * lng[3] + lnb[3], 0.f) + xold.w;
            *(float4*)xr = o;
            *(float4*)(g_agg + (b * NN + row) * DD + td * 4) =
                make_float4(0.f, 0.f, 0.f, 0.f);
        }
    }
}

// ---------------------------------------------------------------------------
// final: out = relu([x ; query] @ mlp_w + mlp_b); query part precomputed.
// ---------------------------------------------------------------------------
__global__ void final_kernel(const float* __restrict__ mlp_w,
                             float* __restrict__ out) {
    extern __shared__ float smem[];
    float* W_s = smem;             // [64][128] = 32KB
    float* x_s = smem + 64 * 128;  // [k][node] = 16KB
    int b = blockIdx.y;
    int n0 = blockIdx.x * 64;
    int t = threadIdx.x;

    const float4* Wg = (const float4*)mlp_w;  // first 64 rows = 2048 float4
    float4* Ws4 = (float4*)W_s;
#pragma unroll
    for (int i = 0; i < 8; i++) Ws4[t + i * 256] = Wg[t + i * 256];

    const float* xb = g_x + (b * NN + n0) * DD;
    int nl = t & 63;
    int c0 = t >> 6;
#pragma unroll
    for (int i = 0; i < 4; i++) {
        int cc = c0 + i * 4;
        float4 v = *(const float4*)&xb[nl * DD + cc * 4];
        x_s[(cc * 4 + 0) * 64 + nl] = v.x;
        x_s[(cc * 4 + 1) * 64 + nl] = v.y;
        x_s[(cc * 4 + 2) * 64 + nl] = v.z;
        x_s[(cc * 4 + 3) * 64 + nl] = v.w;
    }
    __syncthreads();

    int tn = t >> 4;  // 16 node groups (4 nodes each)
    int td = t & 15;  // 16 dim groups (8 dims each)
    float acc[4][8];
#pragma unroll
    for (int i = 0; i < 4; i++)
#pragma unroll
        for (int j = 0; j < 8; j++) acc[i][j] = 0.f;

#pragma unroll 4
    for (int k = 0; k < 64; ++k) {
        const float4 a4 = *(const float4*)(x_s + k * 64 + tn * 4);
        const float4 w0 = *(const float4*)(W_s + k * 128 + td * 8);
        const float4 w1 = *(const float4*)(W_s + k * 128 + td * 8 + 4);
        float aa[4] = {a4.x, a4.y, a4.z, a4.w};
        float ww[8] = {w0.x, w0.y, w0.z, w0.w, w1.x, w1.y, w1.z, w1.w};
#pragma unroll
        for (int i = 0; i < 4; i++)
#pragma unroll
            for (int j = 0; j < 8; j++)
                acc[i][j] = fmaf(aa[i], ww[j], acc[i][j]);
    }

    float qp[8];
    const float4 q0 = *(const float4*)&g_qpart[b * 128 + td * 8];
    const float4 q1 = *(const float4*)&g_qpart[b * 128 + td * 8 + 4];
    qp[0] = q0.x; qp[1] = q0.y; qp[2] = q0.z; qp[3] = q0.w;
    qp[4] = q1.x; qp[5] = q1.y; qp[6] = q1.z; qp[7] = q1.w;

#pragma unroll
    for (int i = 0; i < 4; i++) {
        int n = n0 + tn * 4 + i;
        float* op = out + ((long)(b * NN + n)) * 128 + td * 8;
        float4 o0, o1;
        o0.x = fmaxf(acc[i][0] + qp[0], 0.f);
        o0.y = fmaxf(acc[i][1] + qp[1], 0.f);
        o0.z = fmaxf(acc[i][2] + qp[2], 0.f);
        o0.w = fmaxf(acc[i][3] + qp[3], 0.f);
        o1.x = fmaxf(acc[i][4] + qp[4], 0.f);
        o1.y = fmaxf(acc[i][5] + qp[5], 0.f);
        o1.z = fmaxf(acc[i][6] + qp[6], 0.f);
        o1.w = fmaxf(acc[i][7] + qp[7], 0.f);
        *(float4*)op = o0;
        *(float4*)(op + 4) = o1;
    }
}

// ---------------------------------------------------------------------------
extern "C" void kernel_launch(void* const* d_in, const int* in_sizes, int n_in,
                              void* d_out, int out_size) {
    const float* rel_reps = (const float*)d_in[0];
    const int* h_index = (const int*)d_in[1];
    const int* r_index = (const int*)d_in[2];
    const int* edge_index = (const int*)d_in[3];
    const int* edge_type = (const int*)d_in[4];
    const float* pw1 = (const float*)d_in[5];
    const float* pb1 = (const float*)d_in[6];
    const float* pw2 = (const float*)d_in[7];
    const float* pb2 = (const float*)d_in[8];
    const float* lin_w = (const float*)d_in[9];
    const float* lin_b = (const float*)d_in[10];
    const float* ln_g = (const float*)d_in[11];
    const float* ln_b = (const float*)d_in[12];
    const float* mlp_w = (const float*)d_in[13];
    const float* mlp_b = (const float*)d_in[14];
    float* out = (float*)d_out;

    cudaFuncSetAttribute(linear_kernel,
                         cudaFuncAttributeMaxDynamicSharedMemorySize, 65536);
    cudaFuncSetAttribute(final_kernel,
                         cudaFuncAttributeMaxDynamicSharedMemorySize, 49152);

    prep_kernel<<<1, 256>>>(rel_reps, r_index, h_index, mlp_w, mlp_b, lin_b,
                            ln_g, ln_b);
    init_x<<<(BB * NN * DD / 4 + 255) / 256, 256>>>(h_index);
    for (int l = 0; l < LLAYERS; l++) {
        relproj_kernel<<<BB * RR, 64>>>(rel_reps, pw1, pb1, pw2, pb2, h_index,
                                        l);
        message_kernel<<<(BB * EE + 255) / 256, 256>>>(edge_index, edge_type);
        compact_kernel<<<(BB * NN + 255) / 256, 256>>>();
        linear_kernel<<<dim3((NN + 63) / 64, BB), 256, 65536>>>(lin_w, lin_b,
                                                                ln_g, ln_b, l);
    }
    final_kernel<<<dim3(NN / 64, BB), 256, 49152>>>(mlp_w, out);
}

// round 3
// speedup vs baseline: 1.0824x; 1.0824x over previous
#include <cuda_runtime.h>

#define BB 2
#define NN 40000
#define EE 400000
#define RR 64
#define DD 64
#define LLAYERS 6
#define MASKW 1250  // (NN+31)/32

// Scratch (allocation-free rule: __device__ globals)
__device__ __align__(16) float g_x[BB * NN * DD];    // 20.5 MB
__device__ __align__(16) float g_agg[BB * NN * DD];  // 20.5 MB (invariant: all-zero at launch entry/exit)
__device__ __align__(16) float g_rel[BB * RR * DD];
__device__ __align__(16) float g_query[BB * DD];
__device__ __align__(16) float g_qpart[BB * 2 * DD];
__device__ unsigned g_mask[BB * MASKW];  // bit set => x row may be nonzero
__device__ int g_list[BB * NN];
__device__ int g_count[BB];
__device__ int g_dense;  // 1 => zero rows would produce nonzero output

// ---------------------------------------------------------------------------
// prep: clear masks, query[b] = rel_reps[b, r_index[b]], set h bit,
//       qpart = query @ mlp_w[64:] + mlp_b, dense-fallback flag.
// ---------------------------------------------------------------------------
__global__ void prep_kernel(const float* __restrict__ rel_reps,
                            const int* __restrict__ r_index,
                            const int* __restrict__ h_index,
                            const float* __restrict__ mlp_w,
                            const float* __restrict__ mlp_b,
                            const float* __restrict__ lin_b,
                            const float* __restrict__ ln_g,
                            const float* __restrict__ ln_b) {
    __shared__ float q_s[BB * DD];
    int t = threadIdx.x;  // 256
    for (int i = t; i < BB * MASKW; i += 256) g_mask[i] = 0u;
    if (t < BB * DD) {
        int b = t / DD, d = t % DD;
        float v = rel_reps[(b * RR + r_index[b]) * DD + d];
        g_query[t] = v;
        q_s[t] = v;
    }
    __syncthreads();
    if (t < BB) {
        int h = h_index[t];
        g_mask[t * MASKW + (h >> 5)] = 1u << (h & 31);
    }
    // dense-fallback: would an all-zero input row yield nonzero output?
    if (t == 0) {
        int dense = 0;
        for (int l = 0; l < LLAYERS; l++) {
            const float* lb = lin_b + l * DD;
            float mu = 0.f;
            for (int d = 0; d < DD; d++) mu += lb[d];
            mu *= (1.f / DD);
            float var = 0.f;
            for (int d = 0; d < DD; d++) {
                float dv = lb[d] - mu;
                var += dv * dv;
            }
            var *= (1.f / DD);
            float inv = rsqrtf(var + 1e-5f);
            for (int d = 0; d < DD; d++) {
                float o = (lb[d] - mu) * inv * ln_g[l * DD + d] + ln_b[l * DD + d];
                if (o > 0.f) dense = 1;
            }
        }
        g_dense = dense;
    }
    int b = t / 128, e = t % 128;
    float acc = mlp_b[e];
#pragma unroll
    for (int k = 0; k < DD; k++)
        acc = fmaf(q_s[b * DD + k], mlp_w[(DD + k) * 128 + e], acc);
    g_qpart[b * 128 + e] = acc;
}

// ---------------------------------------------------------------------------
// init x: zeros everywhere, query at h_index[b]
// ---------------------------------------------------------------------------
__global__ void init_x(const int* __restrict__ h_index) {
    int gid = blockIdx.x * 256 + threadIdx.x;
    const int per_b = NN * DD / 4;  // 640000 float4
    if (gid >= BB * per_b) return;
    int b = gid / per_b;
    int r = gid - b * per_b;
    int n = r >> 4;
    int d4 = r & 15;
    float4 v = make_float4(0.f, 0.f, 0.f, 0.f);
    if (n == __ldg(&h_index[b]))
        v = *(const float4*)&g_query[b * DD + d4 * 4];
    ((float4*)g_x)[gid] = v;
}

// ---------------------------------------------------------------------------
// per-layer relation projection + count reset + boundary row agg[b,h]=query
// ---------------------------------------------------------------------------
__global__ void relproj_kernel(const float* __restrict__ rel_reps,
                               const float* __restrict__ pw1,
                               const float* __restrict__ pb1,
                               const float* __restrict__ pw2,
                               const float* __restrict__ pb2,
                               const int* __restrict__ h_index, int l) {
    int br = blockIdx.x;  // b*RR + r
    int b = br >> 6;
    int e = threadIdx.x;  // 64
    __shared__ float in_s[DD];
    __shared__ float hid_s[DD];
    in_s[e] = rel_reps[br * DD + e];
    __syncthreads();
    const float* W1 = pw1 + l * DD * DD;
    float acc = pb1[l * DD + e];
#pragma unroll 16
    for (int k = 0; k < DD; k++) acc = fmaf(in_s[k], W1[k * DD + e], acc);
    hid_s[e] = fmaxf(acc, 0.f);
    __syncthreads();
    const float* W2 = pw2 + l * DD * DD;
    float acc2 = pb2[l * DD + e];
#pragma unroll 16
    for (int k = 0; k < DD; k++) acc2 = fmaf(hid_s[k], W2[k * DD + e], acc2);
    g_rel[br * DD + e] = acc2;

    if ((br & 63) == 0) {
        if (e == 0) g_count[b] = 0;
        int h = __ldg(&h_index[b]);
        g_agg[(b * NN + h) * DD + e] = g_query[b * DD + e];
    }
}

// ---------------------------------------------------------------------------
// message: 4 edges per thread (int4 src load). Inactive src => one mask probe
// only. Active: batch-load all 16 x chunks (MLP=16), then red.v4 per nonzero
// chunk; mark dst active.
// ---------------------------------------------------------------------------
__global__ void message_kernel(const int* __restrict__ edge_index,
                               const int* __restrict__ edge_type) {
    int gid = blockIdx.x * 256 + threadIdx.x;
    const int per_b = EE / 4;  // 100000
    if (gid >= BB * per_b) return;
    int b = (gid >= per_b) ? 1 : 0;
    int e4 = gid - b * per_b;
    const int4 s4 = __ldg((const int4*)edge_index + e4);
    int srcs[4] = {s4.x, s4.y, s4.z, s4.w};
    const unsigned* mask = g_mask + b * MASKW;
#pragma unroll
    for (int j = 0; j < 4; j++) {
        int src = srcs[j];
        if (!((mask[src >> 5] >> (src & 31)) & 1u)) continue;
        int e = e4 * 4 + j;
        int dst = __ldg(&edge_index[EE + e]);
        int ty = __ldg(&edge_type[e]);
        if (!((mask[dst >> 5] >> (dst & 31)) & 1u))
            atomicOr(&g_mask[b * MASKW + (dst >> 5)], 1u << (dst & 31));
        const float4* xr = (const float4*)(g_x + (b * NN + src) * DD);
        const float4* rr = (const float4*)(g_rel + (b * RR + ty) * DD);
        float* ar = g_agg + (b * NN + dst) * DD;
        float4 xv[16];
#pragma unroll
        for (int c = 0; c < 16; c++) xv[c] = xr[c];
#pragma unroll
        for (int c = 0; c < 16; c++) {
            float4 x = xv[c];
            if (x.x == 0.f && x.y == 0.f && x.z == 0.f && x.w == 0.f) continue;
            float4 rv = __ldg(&rr[c]);
            asm volatile(
                "red.global.add.v4.f32 [%0], {%1,%2,%3,%4};" ::"l"(ar + c * 4),
                "f"(x.x * rv.x), "f"(x.y * rv.y), "f"(x.z * rv.z),
                "f"(x.w * rv.w)
                : "memory");
        }
    }
}

// ---------------------------------------------------------------------------
// compact: mask -> list, warp-aggregated (1 atomic per warp, order preserved
// within warp => near-sorted list => coalesced dense gathers).
// NN % 32 == 0, so warps never straddle batches.
// ---------------------------------------------------------------------------
__global__ void compact_kernel() {
    int gid = blockIdx.x * 256 + threadIdx.x;
    if (gid >= BB * NN) return;
    int b = gid / NN;
    int n = gid - b * NN;
    bool act;
    if (g_dense) {
        act = true;
        if ((n & 31) == 0) g_mask[b * MASKW + (n >> 5)] = 0xffffffffu;
    } else {
        act = (g_mask[b * MASKW + (n >> 5)] >> (n & 31)) & 1u;
    }
    unsigned bal = __ballot_sync(0xffffffffu, act);
    if (!bal) return;
    int lane = threadIdx.x & 31;
    int pos = 0;
    if (lane == 0) pos = atomicAdd(&g_count[b], __popc(bal));
    pos = __shfl_sync(0xffffffffu, pos, 0);
    if (act)
        g_list[b * NN + pos + __popc(bal & ((1u << lane) - 1u))] = n;
}

// ---------------------------------------------------------------------------
// fused: for active rows: x = relu(LN(cat(x,agg)@W + b)) + x; agg row -> 0.
// block = 64 list entries, 256 threads, 4x4 register tile per thread.
// ---------------------------------------------------------------------------
__global__ void linear_kernel(const float* __restrict__ lin_w,
                              const float* __restrict__ lin_b,
                              const float* __restrict__ ln_g,
                              const float* __restrict__ ln_b, int l) {
    extern __shared__ float smem[];
    float* W_s = smem;               // [128][64] = 32KB
    float* cat_s = smem + 128 * 64;  // [k][node] transposed = 32KB
    __shared__ int idx_s[64];
    int b = blockIdx.y;
    int base = blockIdx.x * 64;
    int t = threadIdx.x;  // 256
    int cnt = g_count[b];
    if (base >= cnt) return;

    if (t < 64) idx_s[t] = (base + t < cnt) ? g_list[b * NN + base + t] : -1;

    // load weights (8192 floats)
    const float4* Wg = (const float4*)(lin_w + l * 128 * 64);
    float4* Ws4 = (float4*)W_s;
#pragma unroll
    for (int i = 0; i < 8; i++) Ws4[t + i * 256] = Wg[t + i * 256];
    __syncthreads();

    // gather cat = [x ; agg] rows (via list) transposed into smem
    int nl = t & 63;
    int c0 = t >> 6;  // 0..3
    int idx = idx_s[nl];
    const float* xb = g_x + (b * NN + idx) * DD;
    const float* ab = g_agg + (b * NN + idx) * DD;
#pragma unroll
    for (int i = 0; i < 4; i++) {
        int cc = c0 + i * 4;  // float4 col 0..15
        float4 v = make_float4(0.f, 0.f, 0.f, 0.f);
        float4 a = make_float4(0.f, 0.f, 0.f, 0.f);
        if (idx >= 0) {
            v = *(const float4*)&xb[cc * 4];
            a = *(const float4*)&ab[cc * 4];
        }
        cat_s[(cc * 4 + 0) * 64 + nl] = v.x;
        cat_s[(cc * 4 + 1) * 64 + nl] = v.y;
        cat_s[(cc * 4 + 2) * 64 + nl] = v.z;
        cat_s[(cc * 4 + 3) * 64 + nl] = v.w;
        cat_s[(64 + cc * 4 + 0) * 64 + nl] = a.x;
        cat_s[(64 + cc * 4 + 1) * 64 + nl] = a.y;
        cat_s[(64 + cc * 4 + 2) * 64 + nl] = a.z;
        cat_s[(64 + cc * 4 + 3) * 64 + nl] = a.w;
    }
    __syncthreads();

    int tn = t >> 4;  // node group (4 nodes)
    int td = t & 15;  // dim group  (4 dims)
    float4 bias4 = *(const float4*)&lin_b[l * 64 + td * 4];
    float acc[4][4];
#pragma unroll
    for (int i = 0; i < 4; i++) {
        acc[i][0] = bias4.x; acc[i][1] = bias4.y;
        acc[i][2] = bias4.z; acc[i][3] = bias4.w;
    }

#pragma unroll 4
    for (int k = 0; k < 128; ++k) {
        const float4 a4 = *(const float4*)(cat_s + k * 64 + tn * 4);
        const float4 w4 = *(const float4*)(W_s + k * 64 + td * 4);
        float aa[4] = {a4.x, a4.y, a4.z, a4.w};
        float ww[4] = {w4.x, w4.y, w4.z, w4.w};
#pragma unroll
        for (int i = 0; i < 4; i++)
#pragma unroll
            for (int j = 0; j < 4; j++)
                acc[i][j] = fmaf(aa[i], ww[j], acc[i][j]);
    }

    // fused LayerNorm + relu + shortcut; zero agg row for next layer
    float4 g4 = *(const float4*)&ln_g[l * 64 + td * 4];
    float4 bb4 = *(const float4*)&ln_b[l * 64 + td * 4];
    float lng[4] = {g4.x, g4.y, g4.z, g4.w};
    float lnb[4] = {bb4.x, bb4.y, bb4.z, bb4.w};
#pragma unroll
    for (int i = 0; i < 4; i++) {
        float s = acc[i][0] + acc[i][1] + acc[i][2] + acc[i][3];
        float s2 = acc[i][0] * acc[i][0] + acc[i][1] * acc[i][1] +
                   acc[i][2] * acc[i][2] + acc[i][3] * acc[i][3];
#pragma unroll
        for (int m = 1; m < 16; m <<= 1) {
            s += __shfl_xor_sync(0xffffffffu, s, m);
            s2 += __shfl_xor_sync(0xffffffffu, s2, m);
        }
        float mu = s * (1.f / 64.f);
        float var = s2 * (1.f / 64.f) - mu * mu;
        float inv = rsqrtf(var + 1e-5f);
        int row = idx_s[tn * 4 + i];
        if (row >= 0) {
            float* xr = g_x + (b * NN + row) * DD + td * 4;
            float4 xold = *(const float4*)xr;
            float4 o;
            o.x = fmaxf((acc[i][0] - mu) * inv * lng[0] + lnb[0], 0.f) + xold.x;
            o.y = fmaxf((acc[i][1] - mu) * inv * lng[1] + lnb[1], 0.f) + xold.y;
            o.z = fmaxf((acc[i][2] - mu) * inv * lng[2] + lnb[2], 0.f) + xold.z;
            o.w = fmaxf((acc[i][3] - mu) * inv * lng[3] + lnb[3], 0.f) + xold.w;
            *(float4*)xr = o;
            *(float4*)(g_agg + (b * NN + row) * DD + td * 4) =
                make_float4(0.f, 0.f, 0.f, 0.f);
        }
    }
}

// ---------------------------------------------------------------------------
// final: out = relu([x ; query] @ mlp_w + mlp_b); query part precomputed.
// ---------------------------------------------------------------------------
__global__ void final_kernel(const float* __restrict__ mlp_w,
                             float* __restrict__ out) {
    extern __shared__ float smem[];
    float* W_s = smem;             // [64][128] = 32KB
    float* x_s = smem + 64 * 128;  // [k][node] = 16KB
    int b = blockIdx.y;
    int n0 = blockIdx.x * 64;
    int t = threadIdx.x;

    const float4* Wg = (const float4*)mlp_w;  // first 64 rows = 2048 float4
    float4* Ws4 = (float4*)W_s;
#pragma unroll
    for (int i = 0; i < 8; i++) Ws4[t + i * 256] = Wg[t + i * 256];

    const float* xb = g_x + (b * NN + n0) * DD;
    int nl = t & 63;
    int c0 = t >> 6;
#pragma unroll
    for (int i = 0; i < 4; i++) {
        int cc = c0 + i * 4;
        float4 v = *(const float4*)&xb[nl * DD + cc * 4];
        x_s[(cc * 4 + 0) * 64 + nl] = v.x;
        x_s[(cc * 4 + 1) * 64 + nl] = v.y;
        x_s[(cc * 4 + 2) * 64 + nl] = v.z;
        x_s[(cc * 4 + 3) * 64 + nl] = v.w;
    }
    __syncthreads();

    int tn = t >> 4;  // 16 node groups (4 nodes each)
    int td = t & 15;  // 16 dim groups (8 dims each)
    float acc[4][8];
#pragma unroll
    for (int i = 0; i < 4; i++)
#pragma unroll
        for (int j = 0; j < 8; j++) acc[i][j] = 0.f;

#pragma unroll 4
    for (int k = 0; k < 64; ++k) {
        const float4 a4 = *(const float4*)(x_s + k * 64 + tn * 4);
        const float4 w0 = *(const float4*)(W_s + k * 128 + td * 8);
        const float4 w1 = *(const float4*)(W_s + k * 128 + td * 8 + 4);
        float aa[4] = {a4.x, a4.y, a4.z, a4.w};
        float ww[8] = {w0.x, w0.y, w0.z, w0.w, w1.x, w1.y, w1.z, w1.w};
#pragma unroll
        for (int i = 0; i < 4; i++)
#pragma unroll
            for (int j = 0; j < 8; j++)
                acc[i][j] = fmaf(aa[i], ww[j], acc[i][j]);
    }

    float qp[8];
    const float4 q0 = *(const float4*)&g_qpart[b * 128 + td * 8];
    const float4 q1 = *(const float4*)&g_qpart[b * 128 + td * 8 + 4];
    qp[0] = q0.x; qp[1] = q0.y; qp[2] = q0.z; qp[3] = q0.w;
    qp[4] = q1.x; qp[5] = q1.y; qp[6] = q1.z; qp[7] = q1.w;

#pragma unroll
    for (int i = 0; i < 4; i++) {
        int n = n0 + tn * 4 + i;
        float* op = out + ((long)(b * NN + n)) * 128 + td * 8;
        float4 o0, o1;
        o0.x = fmaxf(acc[i][0] + qp[0], 0.f);
        o0.y = fmaxf(acc[i][1] + qp[1], 0.f);
        o0.z = fmaxf(acc[i][2] + qp[2], 0.f);
        o0.w = fmaxf(acc[i][3] + qp[3], 0.f);
        o1.x = fmaxf(acc[i][4] + qp[4], 0.f);
        o1.y = fmaxf(acc[i][5] + qp[5], 0.f);
        o1.z = fmaxf(acc[i][6] + qp[6], 0.f);
        o1.w = fmaxf(acc[i][7] + qp[7], 0.f);
        *(float4*)op = o0;
        *(float4*)(op + 4) = o1;
    }
}

// ---------------------------------------------------------------------------
extern "C" void kernel_launch(void* const* d_in, const int* in_sizes, int n_in,
                              void* d_out, int out_size) {
    const float* rel_reps = (const float*)d_in[0];
    const int* h_index = (const int*)d_in[1];
    const int* r_index = (const int*)d_in[2];
    const int* edge_index = (const int*)d_in[3];
    const int* edge_type = (const int*)d_in[4];
    const float* pw1 = (const float*)d_in[5];
    const float* pb1 = (const float*)d_in[6];
    const float* pw2 = (const float*)d_in[7];
    const float* pb2 = (const float*)d_in[8];
    const float* lin_w = (const float*)d_in[9];
    const float* lin_b = (const float*)d_in[10];
    const float* ln_g = (const float*)d_in[11];
    const float* ln_b = (const float*)d_in[12];
    const float* mlp_w = (const float*)d_in[13];
    const float* mlp_b = (const float*)d_in[14];
    float* out = (float*)d_out;

    cudaFuncSetAttribute(linear_kernel,
                         cudaFuncAttributeMaxDynamicSharedMemorySize, 65536);
    cudaFuncSetAttribute(final_kernel,
                         cudaFuncAttributeMaxDynamicSharedMemorySize, 49152);

    prep_kernel<<<1, 256>>>(rel_reps, r_index, h_index, mlp_w, mlp_b, lin_b,
                            ln_g, ln_b);
    init_x<<<(BB * NN * DD / 4 + 255) / 256, 256>>>(h_index);
    for (int l = 0; l < LLAYERS; l++) {
        relproj_kernel<<<BB * RR, 64>>>(rel_reps, pw1, pb1, pw2, pb2, h_index,
                                        l);
        message_kernel<<<(BB * EE / 4 + 255) / 256, 256>>>(edge_index,
                                                           edge_type);
        compact_kernel<<<(BB * NN + 255) / 256, 256>>>();
        linear_kernel<<<dim3((NN + 63) / 64, BB), 256, 65536>>>(lin_w, lin_b,
                                                                ln_g, ln_b, l);
    }
    final_kernel<<<dim3(NN / 64, BB), 256, 49152>>>(mlp_w, out);
}